// round 6
// baseline (speedup 1.0000x reference)
#include <cuda_runtime.h>
#include <cmath>

// ---------------------------------------------------------------------------
// DecoderRNN: 160-step teacher-forced GRU decoder.
//   h_{t+1} = GRU(h_t, relu(emb[tok_t]));  log_probs_t = log_softmax(h_{t+1} W_out^T + b_out)
// Key algebraic simplifications:
//   * gi = relu(emb[tok]) @ W_ih^T + b_ih depends only on the token value ->
//     precomputed 128x1536 table, gathered per (b, t).
//   * recurrent GEMM h @ W_hh^T done in TF32 on tensor cores (mma.sync.m16n8k4),
//     fp32 accumulate; gates + state update in fp32 fused into the GEMM epilogue.
//   * logits GEMM + log_softmax fused per step.
// Output layout: [160*2048*128 log_probs fp32][2048*512 final hidden fp32]
// ---------------------------------------------------------------------------

#define HID   512
#define VOC   128
#define EMBD  64
#define BSZ   2048
#define TLEN  160
#define G3    1536   // 3*HID

#define AS_LD  36    // A smem row stride (32 + 4 pad)
#define BS_LD  200   // B smem row stride for gru_step (192 + 8 pad)
#define BS2_LD 136   // B smem row stride for logits_step (128 + 8 pad)
#define EP_LD  193   // epilogue smem row stride (192 + 1 pad)

// Scratch (module-load allocated; no runtime allocation)
__device__ float g_Wt [HID * G3];        // W_hh^T, tf32-rounded: [k][n]
__device__ float g_WoT[HID * VOC];       // W_out^T, tf32-rounded: [k][v]
__device__ float g_GI [VOC * G3];        // per-token gi table (includes b_ih)
__device__ float g_H  [2][BSZ * HID];    // fp32 hidden, ping-pong
__device__ float g_Ht [2][BSZ * HID];    // tf32-rounded hidden, ping-pong

__device__ __forceinline__ float tf32r(float x) {
    unsigned u;
    asm("cvt.rna.tf32.f32 %0, %1;" : "=r"(u) : "f"(x));
    return __uint_as_float(u);
}

__device__ __forceinline__ void mma_tf32(float d[4], unsigned a0, unsigned a1, unsigned b0) {
    asm volatile("mma.sync.aligned.m16n8k4.row.col.f32.tf32.tf32.f32 "
                 "{%0,%1,%2,%3}, {%4,%5}, {%6}, {%0,%1,%2,%3};"
                 : "+f"(d[0]), "+f"(d[1]), "+f"(d[2]), "+f"(d[3])
                 : "r"(a0), "r"(a1), "r"(b0));
}

// ---------------------------------------------------------------------------
// Precompute: transposed, tf32-rounded weights
// ---------------------------------------------------------------------------
__global__ void prep_w(const float* __restrict__ Whh, const float* __restrict__ Wout) {
    const int n1 = HID * G3;
    const int ntot = n1 + HID * VOC;
    for (int idx = blockIdx.x * blockDim.x + threadIdx.x; idx < ntot;
         idx += gridDim.x * blockDim.x) {
        if (idx < n1) {
            int n = idx / HID, k = idx % HID;        // read W_hh coalesced
            g_Wt[k * G3 + n] = tf32r(Whh[idx]);
        } else {
            int j = idx - n1;
            int v = j / HID, k = j % HID;
            g_WoT[k * VOC + v] = tf32r(Wout[j]);
        }
    }
}

// GI[v][n] = sum_e relu(emb[v][e]) * W_ih[n][e] + b_ih[n]
__global__ void prep_gi(const float* __restrict__ emb, const float* __restrict__ Wih,
                        const float* __restrict__ bih) {
    __shared__ float x[EMBD];
    const int v = blockIdx.x;
    if (threadIdx.x < EMBD) x[threadIdx.x] = fmaxf(emb[v * EMBD + threadIdx.x], 0.f);
    __syncthreads();
    for (int n = threadIdx.x; n < G3; n += blockDim.x) {
        float acc = bih[n];
        const float* w = Wih + n * EMBD;
#pragma unroll
        for (int e = 0; e < EMBD; e++) acc += x[e] * w[e];
        g_GI[v * G3 + n] = acc;
    }
}

__global__ void init_h(const float* __restrict__ eh) {
    for (int i = blockIdx.x * blockDim.x + threadIdx.x; i < BSZ * HID;
         i += gridDim.x * blockDim.x) {
        float h = eh[i];
        g_H[0][i]  = h;
        g_Ht[0][i] = tf32r(h);
    }
}

// ---------------------------------------------------------------------------
// One GRU step: gh = h @ W_hh^T (TF32 GEMM), fused gate math + state update.
// Grid: (8 j-tiles, 16 m-tiles). CTA tile: M=128 rows x 64 hidden units,
// computing all three 64-wide gate strips (j, j+512, j+1024) -> N=192.
// 8 warps as 4(M) x 2(N); warp tile 32x96; K-tiles of 32, reg-staged pipeline.
// ---------------------------------------------------------------------------
__global__ void __launch_bounds__(256, 1)
gru_step(int t, const int* __restrict__ tgt, const float* __restrict__ bhh) {
    extern __shared__ float sm[];
    float* As = sm;                    // [128][AS_LD]
    float* Bs = sm + 128 * AS_LD;      // [32][BS_LD]
    float* ep = sm;                    // [128][EP_LD] (reused after GEMM)

    const int cur = t & 1, nxt = cur ^ 1;
    const float* __restrict__ A = g_Ht[cur];
    const int tid  = threadIdx.x;
    const int lane = tid & 31, w = tid >> 5;
    const int wm = (w >> 1) * 32;      // warp M offset (0..96)
    const int wn = (w & 1) * 96;       // warp N offset (0 or 96)
    const int m0 = blockIdx.y * 128;
    const int j0 = blockIdx.x * 64;

    float d[2][12][4];
#pragma unroll
    for (int a = 0; a < 2; a++)
#pragma unroll
        for (int b = 0; b < 12; b++)
#pragma unroll
            for (int c = 0; c < 4; c++) d[a][b][c] = 0.f;

    float4 ar[4], br[6];

    // --- prologue: load K-tile 0 into smem ---
#pragma unroll
    for (int i = 0; i < 4; i++) {
        int f = i * 256 + tid, row = f >> 3, c4 = f & 7;
        ar[i] = *reinterpret_cast<const float4*>(A + (m0 + row) * HID + c4 * 4);
    }
#pragma unroll
    for (int i = 0; i < 6; i++) {
        int f = i * 256 + tid, kr = f / 48, cc = f % 48;
        int st = cc >> 4, c4 = cc & 15;
        br[i] = *reinterpret_cast<const float4*>(g_Wt + kr * G3 + j0 + st * 512 + c4 * 4);
    }
#pragma unroll
    for (int i = 0; i < 4; i++) {
        int f = i * 256 + tid, row = f >> 3, c4 = f & 7;
        *reinterpret_cast<float4*>(As + row * AS_LD + c4 * 4) = ar[i];
    }
#pragma unroll
    for (int i = 0; i < 6; i++) {
        int f = i * 256 + tid, kr = f / 48, cc = f % 48;
        int st = cc >> 4, c4 = cc & 15;
        *reinterpret_cast<float4*>(Bs + kr * BS_LD + st * 64 + c4 * 4) = br[i];
    }
    __syncthreads();

    for (int kt = 0; kt < 16; kt++) {
        // stage next K-tile from global while computing current
        if (kt < 15) {
            const int k0 = (kt + 1) * 32;
#pragma unroll
            for (int i = 0; i < 4; i++) {
                int f = i * 256 + tid, row = f >> 3, c4 = f & 7;
                ar[i] = *reinterpret_cast<const float4*>(A + (m0 + row) * HID + k0 + c4 * 4);
            }
#pragma unroll
            for (int i = 0; i < 6; i++) {
                int f = i * 256 + tid, kr = f / 48, cc = f % 48;
                int st = cc >> 4, c4 = cc & 15;
                br[i] = *reinterpret_cast<const float4*>(g_Wt + (k0 + kr) * G3 + j0 + st * 512 + c4 * 4);
            }
        }
        // compute current tile
#pragma unroll
        for (int ks = 0; ks < 8; ks++) {
            const int kk = ks * 4;
            unsigned a0[2], a1[2];
#pragma unroll
            for (int im = 0; im < 2; im++) {
                int row = wm + im * 16 + (lane >> 2);
                a0[im] = __float_as_uint(As[row * AS_LD + kk + (lane & 3)]);
                a1[im] = __float_as_uint(As[(row + 8) * AS_LD + kk + (lane & 3)]);
            }
#pragma unroll
            for (int ib = 0; ib < 12; ib++) {
                unsigned b0 = __float_as_uint(Bs[(kk + (lane & 3)) * BS_LD + wn + ib * 8 + (lane >> 2)]);
                mma_tf32(d[0][ib], a0[0], a1[0], b0);
                mma_tf32(d[1][ib], a0[1], a1[1], b0);
            }
        }
        __syncthreads();
        if (kt < 15) {
#pragma unroll
            for (int i = 0; i < 4; i++) {
                int f = i * 256 + tid, row = f >> 3, c4 = f & 7;
                *reinterpret_cast<float4*>(As + row * AS_LD + c4 * 4) = ar[i];
            }
#pragma unroll
            for (int i = 0; i < 6; i++) {
                int f = i * 256 + tid, kr = f / 48, cc = f % 48;
                int st = cc >> 4, c4 = cc & 15;
                *reinterpret_cast<float4*>(Bs + kr * BS_LD + st * 64 + c4 * 4) = br[i];
            }
            __syncthreads();
        }
    }

    // --- dump gh tile to smem (cols: [0,64)=r strip, [64,128)=z, [128,192)=n) ---
#pragma unroll
    for (int im = 0; im < 2; im++)
#pragma unroll
        for (int ib = 0; ib < 12; ib++)
#pragma unroll
            for (int r = 0; r < 4; r++) {
                int row = wm + im * 16 + (lane >> 2) + ((r >> 1) & 1) * 8;
                int col = wn + ib * 8 + (lane & 3) * 2 + (r & 1);
                ep[row * EP_LD + col] = d[im][ib][r];
            }
    __syncthreads();

    // --- fused GRU update epilogue ---
    const float* __restrict__ Hc  = g_H[cur];
    float* __restrict__ Hn  = g_H[nxt];
    float* __restrict__ Htn = g_Ht[nxt];
    for (int idx = tid; idx < 128 * 64; idx += 256) {
        int m = idx >> 6, jj = idx & 63;
        int b = m0 + m, j = j0 + jj;
        int tok = (t == 0) ? 0 : tgt[b * TLEN + (t - 1)];
        const float* __restrict__ gi = g_GI + tok * G3;
        float gr  = ep[m * EP_LD + jj]        + bhh[j]        + gi[j];
        float gz  = ep[m * EP_LD + 64 + jj]   + bhh[512 + j]  + gi[512 + j];
        float ghn = ep[m * EP_LD + 128 + jj]  + bhh[1024 + j];
        float gin = gi[1024 + j];
        float r = 1.f / (1.f + expf(-gr));
        float z = 1.f / (1.f + expf(-gz));
        float n = tanhf(gin + r * ghn);
        float ho = Hc[b * HID + j];
        float h  = (1.f - z) * n + z * ho;
        Hn[b * HID + j]  = h;
        Htn[b * HID + j] = tf32r(h);
    }
}

// ---------------------------------------------------------------------------
// logits_t = h_{t+1} @ W_out^T + b_out, then row log_softmax (V=128 in-CTA).
// Grid: 32 CTAs (M-tiles of 64). 8 warps as 2(M) x 4(N); warp tile 32x32.
// ---------------------------------------------------------------------------
__global__ void __launch_bounds__(256, 1)
logits_step(int t, const float* __restrict__ bout, float* __restrict__ out) {
    __shared__ float sm2[64 * 129];          // 33 KB; reused as As|Bs then logits
    float* As = sm2;                          // [64][AS_LD]
    float* Bs = sm2 + 64 * AS_LD;             // [32][BS2_LD]
    float* ep = sm2;                          // [64][129]

    const int nxt = (t & 1) ^ 1;
    const float* __restrict__ A = g_Ht[nxt];
    const int tid = threadIdx.x, lane = tid & 31, w = tid >> 5;
    const int wm = (w >> 2) * 32, wn = (w & 3) * 32;
    const int m0 = blockIdx.x * 64;

    float d[2][4][4];
#pragma unroll
    for (int a = 0; a < 2; a++)
#pragma unroll
        for (int b = 0; b < 4; b++)
#pragma unroll
            for (int c = 0; c < 4; c++) d[a][b][c] = 0.f;

    float4 ar[2], br[4];
#pragma unroll
    for (int i = 0; i < 2; i++) {
        int f = i * 256 + tid, row = f >> 3, c4 = f & 7;
        ar[i] = *reinterpret_cast<const float4*>(A + (m0 + row) * HID + c4 * 4);
    }
#pragma unroll
    for (int i = 0; i < 4; i++) {
        int f = i * 256 + tid, kr = f >> 5, c4 = f & 31;
        br[i] = *reinterpret_cast<const float4*>(g_WoT + kr * VOC + c4 * 4);
    }
#pragma unroll
    for (int i = 0; i < 2; i++) {
        int f = i * 256 + tid, row = f >> 3, c4 = f & 7;
        *reinterpret_cast<float4*>(As + row * AS_LD + c4 * 4) = ar[i];
    }
#pragma unroll
    for (int i = 0; i < 4; i++) {
        int f = i * 256 + tid, kr = f >> 5, c4 = f & 31;
        *reinterpret_cast<float4*>(Bs + kr * BS2_LD + c4 * 4) = br[i];
    }
    __syncthreads();

    for (int kt = 0; kt < 16; kt++) {
        if (kt < 15) {
            const int k0 = (kt + 1) * 32;
#pragma unroll
            for (int i = 0; i < 2; i++) {
                int f = i * 256 + tid, row = f >> 3, c4 = f & 7;
                ar[i] = *reinterpret_cast<const float4*>(A + (m0 + row) * HID + k0 + c4 * 4);
            }
#pragma unroll
            for (int i = 0; i < 4; i++) {
                int f = i * 256 + tid, kr = f >> 5, c4 = f & 31;
                br[i] = *reinterpret_cast<const float4*>(g_WoT + (k0 + kr) * VOC + c4 * 4);
            }
        }
#pragma unroll
        for (int ks = 0; ks < 8; ks++) {
            const int kk = ks * 4;
            unsigned a0[2], a1[2];
#pragma unroll
            for (int im = 0; im < 2; im++) {
                int row = wm + im * 16 + (lane >> 2);
                a0[im] = __float_as_uint(As[row * AS_LD + kk + (lane & 3)]);
                a1[im] = __float_as_uint(As[(row + 8) * AS_LD + kk + (lane & 3)]);
            }
#pragma unroll
            for (int ib = 0; ib < 4; ib++) {
                unsigned b0 = __float_as_uint(Bs[(kk + (lane & 3)) * BS2_LD + wn + ib * 8 + (lane >> 2)]);
                mma_tf32(d[0][ib], a0[0], a1[0], b0);
                mma_tf32(d[1][ib], a0[1], a1[1], b0);
            }
        }
        __syncthreads();
        if (kt < 15) {
#pragma unroll
            for (int i = 0; i < 2; i++) {
                int f = i * 256 + tid, row = f >> 3, c4 = f & 7;
                *reinterpret_cast<float4*>(As + row * AS_LD + c4 * 4) = ar[i];
            }
#pragma unroll
            for (int i = 0; i < 4; i++) {
                int f = i * 256 + tid, kr = f >> 5, c4 = f & 31;
                *reinterpret_cast<float4*>(Bs + kr * BS2_LD + c4 * 4) = br[i];
            }
            __syncthreads();
        }
    }

    // dump logits tile
#pragma unroll
    for (int im = 0; im < 2; im++)
#pragma unroll
        for (int ib = 0; ib < 4; ib++)
#pragma unroll
            for (int r = 0; r < 4; r++) {
                int row = wm + im * 16 + (lane >> 2) + ((r >> 1) & 1) * 8;
                int col = wn + ib * 8 + (lane & 3) * 2 + (r & 1);
                ep[row * 129 + col] = d[im][ib][r];
            }
    __syncthreads();

    // row-wise log_softmax (one warp per row, 4 cols per lane)
    float* outt = out + (size_t)t * BSZ * VOC;
    for (int row = w; row < 64; row += 8) {
        float x[4];
        float mx = -1e30f;
#pragma unroll
        for (int q = 0; q < 4; q++) {
            int v = lane + q * 32;
            x[q] = ep[row * 129 + v] + bout[v];
            mx = fmaxf(mx, x[q]);
        }
#pragma unroll
        for (int off = 16; off > 0; off >>= 1)
            mx = fmaxf(mx, __shfl_xor_sync(0xffffffffu, mx, off));
        float s = 0.f;
#pragma unroll
        for (int q = 0; q < 4; q++) s += expf(x[q] - mx);
#pragma unroll
        for (int off = 16; off > 0; off >>= 1)
            s += __shfl_xor_sync(0xffffffffu, s, off);
        float L = mx + logf(s);
        float* orow = outt + (size_t)(m0 + row) * VOC;
#pragma unroll
        for (int q = 0; q < 4; q++) orow[lane + q * 32] = x[q] - L;
    }
}

__global__ void finalize_h(float* __restrict__ out) {
    float* dst = out + (size_t)TLEN * BSZ * VOC;
    for (int i = blockIdx.x * blockDim.x + threadIdx.x; i < BSZ * HID;
         i += gridDim.x * blockDim.x)
        dst[i] = g_H[0][i];     // t=159: nxt = (159&1)^1 = 0
}

// ---------------------------------------------------------------------------
extern "C" void kernel_launch(void* const* d_in, const int* in_sizes, int n_in,
                              void* d_out, int out_size) {
    (void)in_sizes; (void)n_in; (void)out_size;
    // metadata order: encoder_outputs, encoder_hidden, target_tensor, embedding,
    //                 W_ih, W_hh, b_ih, b_hh, W_out, b_out
    const float* enc_h = (const float*)d_in[1];
    const int*   tgt   = (const int*)d_in[2];
    const float* emb   = (const float*)d_in[3];
    const float* Wih   = (const float*)d_in[4];
    const float* Whh   = (const float*)d_in[5];
    const float* bih   = (const float*)d_in[6];
    const float* bhh   = (const float*)d_in[7];
    const float* Wout  = (const float*)d_in[8];
    const float* bout  = (const float*)d_in[9];
    float* out = (float*)d_out;

    // 96.5 KB dynamic smem opt-in (takes effect on the uncaptured correctness call)
    cudaFuncSetAttribute(gru_step, cudaFuncAttributeMaxDynamicSharedMemorySize,
                         128 * EP_LD * 4);

    prep_w <<<512, 256>>>(Whh, Wout);
    prep_gi<<<VOC, 256>>>(emb, Wih, bih);
    init_h <<<1024, 256>>>(enc_h);

    for (int t = 0; t < TLEN; t++) {
        gru_step  <<<dim3(8, 16), 256, 128 * EP_LD * 4>>>(t, tgt, bhh);
        logits_step<<<32, 256>>>(t, bout, out);
    }
    finalize_h<<<1024, 256>>>(out);
}

// round 8
// speedup vs baseline: 1.9807x; 1.9807x over previous
#include <cuda_runtime.h>
#include <cmath>

// ---------------------------------------------------------------------------
// DecoderRNN:
//  * gi table precompute (token -> 1536 gate inputs)
//  * per-step fused GEMM+GRU: m16n8k8 TF32 mma, cp.async double-buffered smem,
//    512 threads/CTA, gate-interleaved B layout -> register-only epilogue
//  * all 160 hidden states stored (tf32) -> ONE batched logits GEMM + fused
//    log_softmax at the end
// Output: [160*2048*128 log_probs fp32][2048*512 final hidden fp32]
// ---------------------------------------------------------------------------

#define HID   512
#define VOC   128
#define EMBD  64
#define BSZ   2048
#define TLEN  160
#define G3    1536

#define AS_LD  36      // A smem row stride (32 + 4)
#define BS_LD  200     // gru B smem row stride (192 + 8)
#define BS2_LD 136     // logits B smem row stride (128 + 8)
#define EP_LD  132     // logits epilogue stride

#define SBUF   (128 * AS_LD + 32 * BS_LD)    // 11008 floats per gru stage
#define SBUF2  (128 * AS_LD + 32 * BS2_LD)   // 8960 floats per logits stage

// Static scratch (module-load allocated)
__device__ float g_Wt  [HID * G3];                       // W_hh^T tf32 [k][n]
__device__ float g_WoT [HID * VOC];                      // W_out^T tf32 [k][v]
__device__ float g_GI  [VOC * G3];                       // gi table (incl b_ih)
__device__ float g_H   [2][BSZ * HID];                   // fp32 hidden ping-pong
__device__ float g_Hall[(size_t)(TLEN + 1) * BSZ * HID]; // tf32 hidden history

__device__ __forceinline__ float tf32r(float x) {
    unsigned u;
    asm("cvt.rna.tf32.f32 %0, %1;" : "=r"(u) : "f"(x));
    return __uint_as_float(u);
}

__device__ __forceinline__ void cpa16(float* dst, const float* src) {
    unsigned d = (unsigned)__cvta_generic_to_shared(dst);
    asm volatile("cp.async.cg.shared.global [%0], [%1], 16;" :: "r"(d), "l"(src));
}
#define CP_COMMIT() asm volatile("cp.async.commit_group;")
#define CP_WAIT0()  asm volatile("cp.async.wait_group 0;")

__device__ __forceinline__ void mma8(float d[4], const unsigned a[4],
                                     unsigned b0, unsigned b1) {
    asm volatile("mma.sync.aligned.m16n8k8.row.col.f32.tf32.tf32.f32 "
                 "{%0,%1,%2,%3}, {%4,%5,%6,%7}, {%8,%9}, {%0,%1,%2,%3};"
                 : "+f"(d[0]), "+f"(d[1]), "+f"(d[2]), "+f"(d[3])
                 : "r"(a[0]), "r"(a[1]), "r"(a[2]), "r"(a[3]), "r"(b0), "r"(b1));
}

// ---------------------------------------------------------------------------
// Precompute
// ---------------------------------------------------------------------------
__global__ void prep_w(const float* __restrict__ Whh, const float* __restrict__ Wout) {
    const int n1 = HID * G3, ntot = n1 + HID * VOC;
    for (int idx = blockIdx.x * blockDim.x + threadIdx.x; idx < ntot;
         idx += gridDim.x * blockDim.x) {
        if (idx < n1) {
            int n = idx / HID, k = idx % HID;
            g_Wt[k * G3 + n] = tf32r(Whh[idx]);
        } else {
            int j = idx - n1, v = j / HID, k = j % HID;
            g_WoT[k * VOC + v] = tf32r(Wout[j]);
        }
    }
}

__global__ void prep_gi(const float* __restrict__ emb, const float* __restrict__ Wih,
                        const float* __restrict__ bih) {
    __shared__ float x[EMBD];
    const int v = blockIdx.x;
    if (threadIdx.x < EMBD) x[threadIdx.x] = fmaxf(emb[v * EMBD + threadIdx.x], 0.f);
    __syncthreads();
    for (int n = threadIdx.x; n < G3; n += blockDim.x) {
        float acc = bih[n];
        const float* w = Wih + n * EMBD;
#pragma unroll
        for (int e = 0; e < EMBD; e++) acc += x[e] * w[e];
        g_GI[v * G3 + n] = acc;
    }
}

__global__ void init_h(const float* __restrict__ eh) {
    for (int i = blockIdx.x * blockDim.x + threadIdx.x; i < BSZ * HID;
         i += gridDim.x * blockDim.x) {
        float h = eh[i];
        g_H[0][i]   = h;
        g_Hall[i]   = tf32r(h);   // slot 0
    }
}

// ---------------------------------------------------------------------------
// GRU step. Grid (8 j-tiles, 16 m-tiles), 512 threads = 16 warps (4M x 4N).
// CTA tile: 128 rows x 64 hidden cols x 3 gates (N=192, gate-interleaved).
// Warp tile: 32(M) x 48(N) = 16 jj x 3 gates -> register GRU epilogue.
// ---------------------------------------------------------------------------
__global__ void __launch_bounds__(512, 1)
gru_step(int t, const int* __restrict__ tgt, const float* __restrict__ bhh) {
    extern __shared__ float sm[];

    const int tid  = threadIdx.x;
    const int lane = tid & 31, w = tid >> 5;
    const int l3 = lane & 3, q2 = lane >> 2;
    const int wm = (w >> 2) * 32;      // warp M offset
    const int wn = (w & 3);            // warp N group (16 jj cols)
    const int m0 = blockIdx.y * 128;
    const int j0 = blockIdx.x * 64;

    const int cur = t & 1, nxt = cur ^ 1;
    const float* __restrict__ A = g_Hall + (size_t)t * BSZ * HID;

    float d[2][6][4];
#pragma unroll
    for (int a = 0; a < 2; a++)
#pragma unroll
        for (int b = 0; b < 6; b++)
#pragma unroll
            for (int c = 0; c < 4; c++) d[a][b][c] = 0.f;

    // ---- tile loader (cp.async) ----
    auto load_tile = [&](int buf, int k0) {
        float* As = sm + buf * SBUF;
        float* Bs = As + 128 * AS_LD;
#pragma unroll
        for (int i = 0; i < 2; i++) {              // A: 128x32  (rows m0..m0+127)
            int f = i * 512 + tid, row = f >> 3, q = f & 7;
            cpa16(As + row * AS_LD + q * 4,
                  A + (size_t)(m0 + row) * HID + k0 + q * 4);   // <-- m0 FIX
        }
#pragma unroll
        for (int i = 0; i < 3; i++) {              // B: 32x192 gate-interleaved
            int f = i * 512 + tid;
            int k = f / 48, rest = f % 48;
            int g = rest >> 4, q = rest & 15;
            int c = (q >> 2) * 48 + g * 16 + (q & 3) * 4;
            cpa16(Bs + k * BS_LD + c,
                  g_Wt + (size_t)(k0 + k) * G3 + g * HID + j0 + q * 4);
        }
    };

    load_tile(0, 0);
    CP_COMMIT();
    CP_WAIT0();
    __syncthreads();

    for (int kt = 0; kt < 16; kt++) {
        if (kt < 15) { load_tile((kt + 1) & 1, (kt + 1) * 32); CP_COMMIT(); }
        const float* As = sm + (kt & 1) * SBUF;
        const float* Bs = As + 128 * AS_LD;
#pragma unroll
        for (int ks = 0; ks < 4; ks++) {
            const int kk = ks * 8;
            unsigned a[2][4];
#pragma unroll
            for (int mf = 0; mf < 2; mf++) {
                int row = wm + mf * 16 + q2;
                a[mf][0] = __float_as_uint(As[row * AS_LD + kk + l3]);
                a[mf][1] = __float_as_uint(As[(row + 8) * AS_LD + kk + l3]);
                a[mf][2] = __float_as_uint(As[row * AS_LD + kk + 4 + l3]);
                a[mf][3] = __float_as_uint(As[(row + 8) * AS_LD + kk + 4 + l3]);
            }
#pragma unroll
            for (int nf = 0; nf < 6; nf++) {
                int col = wn * 48 + nf * 8 + q2;
                unsigned b0 = __float_as_uint(Bs[(kk + l3) * BS_LD + col]);
                unsigned b1 = __float_as_uint(Bs[(kk + 4 + l3) * BS_LD + col]);
                mma8(d[0][nf], a[0], b0, b1);
                mma8(d[1][nf], a[1], b0, b1);
            }
        }
        if (kt < 15) { CP_WAIT0(); __syncthreads(); }
    }

    // ---- register GRU epilogue (precise transcendentals, as in passing R6) ----
    const float* __restrict__ Hc = g_H[cur];
    float* __restrict__ Hn  = g_H[nxt];
    float* __restrict__ Ha  = g_Hall + (size_t)(t + 1) * BSZ * HID;
#pragma unroll
    for (int mf = 0; mf < 2; mf++) {
#pragma unroll
        for (int rh = 0; rh < 2; rh++) {
            const int row = m0 + wm + mf * 16 + q2 + rh * 8;
            const int tok = (t == 0) ? 0 : __ldg(tgt + row * TLEN + t - 1);
            const float* __restrict__ gi = g_GI + tok * G3;
#pragma unroll
            for (int jf = 0; jf < 2; jf++) {
#pragma unroll
                for (int p = 0; p < 2; p++) {
                    const int r  = rh * 2 + p;
                    const int j  = j0 + wn * 16 + jf * 8 + l3 * 2 + p;
                    float gr  = d[mf][jf][r]     + bhh[j]         + gi[j];
                    float gz  = d[mf][2 + jf][r] + bhh[HID + j]   + gi[HID + j];
                    float ghn = d[mf][4 + jf][r] + bhh[2*HID + j];
                    float rr = 1.f / (1.f + expf(-gr));
                    float zz = 1.f / (1.f + expf(-gz));
                    float nn = tanhf(gi[2*HID + j] + rr * ghn);
                    float ho = Hc[row * HID + j];
                    float h  = fmaf(zz, ho - nn, nn);   // (1-z)n + z*ho
                    Hn[row * HID + j] = h;
                    Ha[(size_t)row * HID + j] = tf32r(h);
                }
            }
        }
    }
}

// ---------------------------------------------------------------------------
// Batched logits: (160*2048) x 128 x 512 GEMM + fused row log_softmax.
// Grid 2560 (M-tiles of 128). 256 threads = 8 warps (4M x 2N), warp 32x64.
// ---------------------------------------------------------------------------
__global__ void __launch_bounds__(256, 1)
logits_all(const float* __restrict__ bout, float* __restrict__ out) {
    extern __shared__ float sm[];
    float* ep = sm;                                 // reused after GEMM

    const int tid  = threadIdx.x;
    const int lane = tid & 31, w = tid >> 5;
    const int l3 = lane & 3, q2 = lane >> 2;
    const int wm = (w >> 1) * 32;
    const int wn = (w & 1) * 64;
    const int m0 = blockIdx.x * 128;                // global row (t*2048+b)

    const float* __restrict__ A = g_Hall + (size_t)BSZ * HID;  // slots 1..160

    float d[2][8][4];
#pragma unroll
    for (int a = 0; a < 2; a++)
#pragma unroll
        for (int b = 0; b < 8; b++)
#pragma unroll
            for (int c = 0; c < 4; c++) d[a][b][c] = 0.f;

    auto load_tile = [&](int buf, int k0) {
        float* As = sm + buf * SBUF2;
        float* Bs = As + 128 * AS_LD;
#pragma unroll
        for (int i = 0; i < 4; i++) {               // A: 128x32
            int f = i * 256 + tid, row = f >> 3, q = f & 7;
            cpa16(As + row * AS_LD + q * 4,
                  A + (size_t)(m0 + row) * HID + k0 + q * 4);
        }
#pragma unroll
        for (int i = 0; i < 4; i++) {               // B: 32x128
            int f = i * 256 + tid, k = f >> 5, q = f & 31;
            cpa16(Bs + k * BS2_LD + q * 4, g_WoT + (k0 + k) * VOC + q * 4);
        }
    };

    load_tile(0, 0);
    CP_COMMIT();
    CP_WAIT0();
    __syncthreads();

    for (int kt = 0; kt < 16; kt++) {
        if (kt < 15) { load_tile((kt + 1) & 1, (kt + 1) * 32); CP_COMMIT(); }
        const float* As = sm + (kt & 1) * SBUF2;
        const float* Bs = As + 128 * AS_LD;
#pragma unroll
        for (int ks = 0; ks < 4; ks++) {
            const int kk = ks * 8;
            unsigned a[2][4];
#pragma unroll
            for (int mf = 0; mf < 2; mf++) {
                int row = wm + mf * 16 + q2;
                a[mf][0] = __float_as_uint(As[row * AS_LD + kk + l3]);
                a[mf][1] = __float_as_uint(As[(row + 8) * AS_LD + kk + l3]);
                a[mf][2] = __float_as_uint(As[row * AS_LD + kk + 4 + l3]);
                a[mf][3] = __float_as_uint(As[(row + 8) * AS_LD + kk + 4 + l3]);
            }
#pragma unroll
            for (int nf = 0; nf < 8; nf++) {
                int col = wn + nf * 8 + q2;
                unsigned b0 = __float_as_uint(Bs[(kk + l3) * BS2_LD + col]);
                unsigned b1 = __float_as_uint(Bs[(kk + 4 + l3) * BS2_LD + col]);
                mma8(d[0][nf], a[0], b0, b1);
                mma8(d[1][nf], a[1], b0, b1);
            }
        }
        if (kt < 15) { CP_WAIT0(); __syncthreads(); }
    }

    __syncthreads();   // all warps done with smem buffers before ep reuse

    // dump logits tile (float2 stores: adjacent col pairs)
#pragma unroll
    for (int mf = 0; mf < 2; mf++)
#pragma unroll
        for (int nf = 0; nf < 8; nf++)
#pragma unroll
            for (int rh = 0; rh < 2; rh++) {
                int row = wm + mf * 16 + q2 + rh * 8;
                int col = wn + nf * 8 + l3 * 2;
                *reinterpret_cast<float2*>(ep + row * EP_LD + col) =
                    make_float2(d[mf][nf][rh * 2], d[mf][nf][rh * 2 + 1]);
            }
    __syncthreads();

    // fused log_softmax: each warp owns 16 contiguous rows
    for (int i = 0; i < 16; i++) {
        int row = w * 16 + i;
        float x[4];
        float mx = -1e30f;
#pragma unroll
        for (int q = 0; q < 4; q++) {
            int v = lane + q * 32;
            x[q] = ep[row * EP_LD + v] + bout[v];
            mx = fmaxf(mx, x[q]);
        }
#pragma unroll
        for (int off = 16; off > 0; off >>= 1)
            mx = fmaxf(mx, __shfl_xor_sync(0xffffffffu, mx, off));
        float s = 0.f;
#pragma unroll
        for (int q = 0; q < 4; q++) s += expf(x[q] - mx);
#pragma unroll
        for (int off = 16; off > 0; off >>= 1)
            s += __shfl_xor_sync(0xffffffffu, s, off);
        float L = mx + logf(s);
        float* orow = out + (size_t)(m0 + row) * VOC;
#pragma unroll
        for (int q = 0; q < 4; q++) orow[lane + q * 32] = x[q] - L;
    }
}

__global__ void finalize_h(float* __restrict__ out) {
    float* dst = out + (size_t)TLEN * BSZ * VOC;
    for (int i = blockIdx.x * blockDim.x + threadIdx.x; i < BSZ * HID;
         i += gridDim.x * blockDim.x)
        dst[i] = g_H[0][i];   // after t=159: nxt = (159&1)^1 = 0
}

// ---------------------------------------------------------------------------
extern "C" void kernel_launch(void* const* d_in, const int* in_sizes, int n_in,
                              void* d_out, int out_size) {
    (void)in_sizes; (void)n_in; (void)out_size;
    const float* enc_h = (const float*)d_in[1];
    const int*   tgt   = (const int*)d_in[2];
    const float* emb   = (const float*)d_in[3];
    const float* Wih   = (const float*)d_in[4];
    const float* Whh   = (const float*)d_in[5];
    const float* bih   = (const float*)d_in[6];
    const float* bhh   = (const float*)d_in[7];
    const float* Wout  = (const float*)d_in[8];
    const float* bout  = (const float*)d_in[9];
    float* out = (float*)d_out;

    const int gru_smem = 2 * SBUF  * 4;   // 88064 B
    const int log_smem = 2 * SBUF2 * 4;   // 71680 B (>= 128*EP_LD*4 = 67584)
    cudaFuncSetAttribute(gru_step,   cudaFuncAttributeMaxDynamicSharedMemorySize, gru_smem);
    cudaFuncSetAttribute(logits_all, cudaFuncAttributeMaxDynamicSharedMemorySize, log_smem);

    prep_w <<<512, 256>>>(Whh, Wout);
    prep_gi<<<VOC, 256>>>(emb, Wih, bih);
    init_h <<<1024, 256>>>(enc_h);

    for (int t = 0; t < TLEN; t++)
        gru_step<<<dim3(8, 16), 512, gru_smem>>>(t, tgt, bhh);

    logits_all<<<(TLEN * BSZ) / 128, 256, log_smem>>>(bout, out);
    finalize_h<<<1024, 256>>>(out);
}